// round 9
// baseline (speedup 1.0000x reference)
#include <cuda_runtime.h>
#include <cuda_fp16.h>
#include <math.h>
#include <stdint.h>

#define NTOK 4096
#define DDIM 1024
#define NEXP 8
#define HDIM 4096
#define BKH 64            // k per tile (halves)
#define CONVBLKS 1024
#define SPLITK 2
#define KSLICE (HDIM / SPLITK)

// ---------------- scratch ----------------
__device__ __half g_xnh[(size_t)NTOK * DDIM];                  // normalized x, fp16
__device__ __half g_w1h[(size_t)NEXP * DDIM * HDIM];           // w1 fp16
__device__ __half g_w2h[(size_t)NEXP * HDIM * DDIM];           // w2 fp16
__device__ __half g_h[(size_t)NEXP * NTOK * HDIM];             // hidden, fp16
__device__ int    g_cnt[NEXP];
__device__ float  g_psum[NEXP];
__device__ int    g_tok[NEXP * NTOK];
__device__ float  g_gate[NEXP * NTOK];

// ---------------- helpers ----------------
__device__ __forceinline__ uint32_t smem_u32(const void* p) {
    uint32_t a;
    asm("{ .reg .u64 t; cvta.to.shared.u64 t, %1; cvt.u32.u64 %0, t; }" : "=r"(a) : "l"(p));
    return a;
}
__device__ __forceinline__ uint32_t pack_h2(float a, float b) {
    __half2 h = __floats2half2_rn(a, b);
    return *(uint32_t*)&h;
}
#define CP16(dst, src) \
    asm volatile("cp.async.ca.shared.global [%0], [%1], 16;" :: "r"(dst), "l"(src))
#define CP16Z(dst, src, bytes) \
    asm volatile("cp.async.ca.shared.global [%0], [%1], 16, %2;" :: "r"(dst), "l"(src), "r"(bytes))
#define CP_COMMIT() asm volatile("cp.async.commit_group;" ::: "memory")
#define CP_WAIT1()  asm volatile("cp.async.wait_group 1;" ::: "memory")

#define LDSM_X4(r0, r1, r2, r3, addr) \
    asm volatile("ldmatrix.sync.aligned.m8n8.x4.shared.b16 {%0,%1,%2,%3}, [%4];" \
        : "=r"(r0), "=r"(r1), "=r"(r2), "=r"(r3) : "r"(addr))
#define LDSM_X4T(r0, r1, r2, r3, addr) \
    asm volatile("ldmatrix.sync.aligned.m8n8.x4.trans.shared.b16 {%0,%1,%2,%3}, [%4];" \
        : "=r"(r0), "=r"(r1), "=r"(r2), "=r"(r3) : "r"(addr))

__device__ __forceinline__ void mma_f16(float* d, const uint32_t* a, const uint32_t* b) {
    asm volatile(
        "mma.sync.aligned.m16n8k16.row.col.f32.f16.f16.f32 "
        "{%0,%1,%2,%3}, {%4,%5,%6,%7}, {%8,%9}, {%0,%1,%2,%3};"
        : "+f"(d[0]), "+f"(d[1]), "+f"(d[2]), "+f"(d[3])
        : "r"(a[0]), "r"(a[1]), "r"(a[2]), "r"(a[3]), "r"(b[0]), "r"(b[1]));
}

// CTA tile 128x64, 4 warps (2m x 2n), warp tile 64x32, 2-stage ring.
// smem strides in halves: 72h = 144B; 144 mod 128 = 16 -> conflict-free ldsm/STS
#define AST 72
#define BST 72
#define ABUF_H (128 * AST)   // 9216 halves / stage
#define BBUF_H (BKH * BST)   // 4608 halves / stage
#define NSTAGE 2
#define SMEM_BYTES ((NSTAGE * (ABUF_H + BBUF_H)) * 2 + 64)

// ---------------- reset counters ----------------
__global__ void zero_kernel() {
    int t = threadIdx.x;
    if (t < NEXP) { g_cnt[t] = 0; g_psum[t] = 0.0f; }
}

// ---------------- merged prep: LN+router+residual copy, + w1 convert ----------
__global__ __launch_bounds__(256) void prep_kernel(
    const float* __restrict__ x, const float* __restrict__ gamma,
    const float* __restrict__ beta, const float* __restrict__ gw,
    const float4* __restrict__ w1,
    float* __restrict__ out, float* __restrict__ probs_out)
{
    const int tid = threadIdx.x;

    if (blockIdx.x >= NTOK) {
        // w1 convert only (w2 converts inside gemm1's grid)
        const int n4 = NEXP * DDIM * HDIM / 4;
        uint2* o1 = (uint2*)g_w1h;
        for (int i = (blockIdx.x - NTOK) * 256 + tid; i < n4;
             i += CONVBLKS * 256) {
            float4 v = w1[i];
            uint2 o;
            o.x = pack_h2(v.x, v.y);
            o.y = pack_h2(v.z, v.w);
            o1[i] = o;
        }
        return;
    }

    const int n = blockIdx.x;
    const int lane = tid & 31, warp = tid >> 5;

    float4 v = reinterpret_cast<const float4*>(x + (size_t)n * DDIM)[tid];
    // residual base: out = x
    reinterpret_cast<float4*>(out + (size_t)n * DDIM)[tid] = v;

    float s  = v.x + v.y + v.z + v.w;
    float ss = v.x * v.x + v.y * v.y + v.z * v.z + v.w * v.w;

    __shared__ float rs[8], rss[8];
    #pragma unroll
    for (int o = 16; o; o >>= 1) {
        s  += __shfl_down_sync(0xffffffffu, s, o);
        ss += __shfl_down_sync(0xffffffffu, ss, o);
    }
    if (lane == 0) { rs[warp] = s; rss[warp] = ss; }
    __syncthreads();

    __shared__ float s_mu, s_rstd;
    if (tid == 0) {
        float S = 0.f, SS = 0.f;
        #pragma unroll
        for (int i = 0; i < 8; i++) { S += rs[i]; SS += rss[i]; }
        float mu = S / (float)DDIM;
        float var = SS / (float)DDIM - mu * mu;
        s_mu = mu; s_rstd = rsqrtf(var + 1e-5f);
    }
    __syncthreads();
    const float mu = s_mu, r = s_rstd;

    float4 g4 = reinterpret_cast<const float4*>(gamma)[tid];
    float4 b4 = reinterpret_cast<const float4*>(beta)[tid];
    float xn0 = (v.x - mu) * r * g4.x + b4.x;
    float xn1 = (v.y - mu) * r * g4.y + b4.y;
    float xn2 = (v.z - mu) * r * g4.z + b4.z;
    float xn3 = (v.w - mu) * r * g4.w + b4.w;
    {
        uint2 o;
        o.x = pack_h2(xn0, xn1);
        o.y = pack_h2(xn2, xn3);
        reinterpret_cast<uint2*>(g_xnh + (size_t)n * DDIM)[tid] = o;
    }

    float lg[NEXP];
    {
        const float4* gwr = reinterpret_cast<const float4*>(gw + (size_t)tid * 4 * NEXP);
        float4 a0 = gwr[0], a1 = gwr[1];
        float4 c0 = gwr[2], c1 = gwr[3];
        float4 d0 = gwr[4], d1 = gwr[5];
        float4 e0 = gwr[6], e1 = gwr[7];
        lg[0] = xn0*a0.x + xn1*c0.x + xn2*d0.x + xn3*e0.x;
        lg[1] = xn0*a0.y + xn1*c0.y + xn2*d0.y + xn3*e0.y;
        lg[2] = xn0*a0.z + xn1*c0.z + xn2*d0.z + xn3*e0.z;
        lg[3] = xn0*a0.w + xn1*c0.w + xn2*d0.w + xn3*e0.w;
        lg[4] = xn0*a1.x + xn1*c1.x + xn2*d1.x + xn3*e1.x;
        lg[5] = xn0*a1.y + xn1*c1.y + xn2*d1.y + xn3*e1.y;
        lg[6] = xn0*a1.z + xn1*c1.z + xn2*d1.z + xn3*e1.z;
        lg[7] = xn0*a1.w + xn1*c1.w + xn2*d1.w + xn3*e1.w;
    }

    __shared__ float sl[8][NEXP];
    #pragma unroll
    for (int e = 0; e < NEXP; e++) {
        float t = lg[e];
        #pragma unroll
        for (int o = 16; o; o >>= 1) t += __shfl_down_sync(0xffffffffu, t, o);
        if (lane == 0) sl[warp][e] = t;
    }
    __syncthreads();

    if (tid == 0) {
        float logit[NEXP];
        #pragma unroll
        for (int e = 0; e < NEXP; e++) {
            float t = 0.f;
            #pragma unroll
            for (int w = 0; w < 8; w++) t += sl[w][e];
            logit[e] = t;
        }
        float mx = logit[0];
        #pragma unroll
        for (int e = 1; e < NEXP; e++) mx = fmaxf(mx, logit[e]);
        float p[NEXP], denom = 0.f;
        #pragma unroll
        for (int e = 0; e < NEXP; e++) { p[e] = expf(logit[e] - mx); denom += p[e]; }
        float inv = 1.0f / denom;
        #pragma unroll
        for (int e = 0; e < NEXP; e++) {
            p[e] *= inv;
            probs_out[(size_t)n * NEXP + e] = p[e];
            atomicAdd(&g_psum[e], p[e]);
        }
        int i1 = 0;
        #pragma unroll
        for (int e = 1; e < NEXP; e++) if (p[e] > p[i1]) i1 = e;
        int i2 = (i1 == 0) ? 1 : 0;
        #pragma unroll
        for (int e = 0; e < NEXP; e++) if (e != i1 && p[e] > p[i2]) i2 = e;
        float wsum = p[i1] + p[i2] + 1e-8f;
        float w1v = p[i1] / wsum, w2v = p[i2] / wsum;
        int r1 = atomicAdd(&g_cnt[i1], 1);
        g_tok[i1 * NTOK + r1] = n; g_gate[i1 * NTOK + r1] = w1v;
        int r2 = atomicAdd(&g_cnt[i2], 1);
        g_tok[i2 * NTOK + r2] = n; g_gate[i2 * NTOK + r2] = w2v;
    }
}

// ============ fp16 HMMA GEMM core: BM=128, BN=64, BK=64, 128 threads ============
// 4 warps (2m x 2n), warp tile 64x32, 2-stage ring, 4 CTAs/SM.

__device__ __forceinline__ void gemm_mainloop(
    uint32_t sA, uint32_t sB,
    const __half* aptr, uint32_t abytes,    // this thread's gathered A row
    const __half* bptr, size_t b_adv,       // this thread's B source
    int NK, float acc[4][4][4])
{
    const int tid = threadIdx.x;
    const int lane = tid & 31;
    const int warp = tid >> 5;              // 0..3
    const int wm64 = (warp >> 1) * 64;
    const int wn32 = (warp & 1) * 32;

    // loader smem offsets (bytes into stage)
    const uint32_t a_soff = (uint32_t)(tid * AST * 2);                       // row tid
    const uint32_t b_soff = (uint32_t)(((tid >> 1) * BST + (tid & 1) * 32) * 2);

    // ldmatrix lane offsets
    const int lrow = (lane & 7) + 8 * ((lane >> 3) & 1);
    const int lhi  = 8 * (lane >> 4);
    uint32_t aoff[4], boff[2];
    #pragma unroll
    for (int mt = 0; mt < 4; mt++)
        aoff[mt] = (uint32_t)(((wm64 + mt * 16 + lrow) * AST + lhi) * 2);
    #pragma unroll
    for (int np = 0; np < 2; np++)
        boff[np] = (uint32_t)((lrow * BST + wn32 + np * 16 + lhi) * 2);

    // prologue: stage 0
    {
        uint32_t dA = sA + a_soff;
        uint32_t dB = sB + b_soff;
        #pragma unroll
        for (int j = 0; j < 8; j++)
            CP16Z(dA + j * 16, aptr + j * 8, abytes);
        aptr += BKH;
        #pragma unroll
        for (int j = 0; j < 4; j++)
            CP16(dB + j * 16, bptr + j * 8);
        bptr += b_adv;
        CP_COMMIT();
    }

    for (int ic = 0; ic < NK; ic++) {
        // barrier A: everyone done reading the buffer we're about to overwrite
        __syncthreads();
        if (ic + 1 < NK) {
            const int st = (ic + 1) & 1;
            uint32_t dA = sA + st * (ABUF_H * 2) + a_soff;
            uint32_t dB = sB + st * (BBUF_H * 2) + b_soff;
            #pragma unroll
            for (int j = 0; j < 8; j++)
                CP16Z(dA + j * 16, aptr + j * 8, abytes);
            aptr += BKH;
            #pragma unroll
            for (int j = 0; j < 4; j++)
                CP16(dB + j * 16, bptr + j * 8);
            bptr += b_adv;
        }
        CP_COMMIT();
        CP_WAIT1();            // stage ic data (own writes) complete
        // barrier B: all warps' stage-ic writes visible
        __syncthreads();

        const uint32_t sAt = sA + (ic & 1) * (ABUF_H * 2);
        const uint32_t sBt = sB + (ic & 1) * (BBUF_H * 2);
        #pragma unroll
        for (int ks = 0; ks < 4; ks++) {
            uint32_t af[4][4], bf[2][4];
            #pragma unroll
            for (int mt = 0; mt < 4; mt++)
                LDSM_X4(af[mt][0], af[mt][1], af[mt][2], af[mt][3],
                        sAt + aoff[mt] + ks * 32);
            #pragma unroll
            for (int np = 0; np < 2; np++)
                LDSM_X4T(bf[np][0], bf[np][1], bf[np][2], bf[np][3],
                         sBt + boff[np] + ks * 16 * BST * 2);
            #pragma unroll
            for (int mt = 0; mt < 4; mt++)
                #pragma unroll
                for (int nt = 0; nt < 4; nt++)
                    mma_f16(acc[mt][nt], af[mt], &bf[nt >> 1][(nt & 1) * 2]);
        }
    }
}

// ============ GEMM 1: g_h = gelu(gather(g_xnh) @ w1h + b1)  (+ w2 convert) ====
__global__ __launch_bounds__(128, 4) void gemm1_kernel(
    const float* __restrict__ b1, const float4* __restrict__ w2)
{
    const int tid = threadIdx.x;

    if (blockIdx.z == NEXP) {
        // w2 fp32->fp16 convert riding in gemm1's grid
        const int n4 = NEXP * HDIM * DDIM / 4;
        uint2* o2 = (uint2*)g_w2h;
        const int nblk = gridDim.x * gridDim.y;
        const int bid = blockIdx.y * gridDim.x + blockIdx.x;
        for (int i = bid * 128 + tid; i < n4; i += nblk * 128) {
            float4 v = w2[i];
            uint2 o;
            o.x = pack_h2(v.x, v.y);
            o.y = pack_h2(v.z, v.w);
            o2[i] = o;
        }
        return;
    }

    const int e = blockIdx.z;
    const int cnt = g_cnt[e];
    const int m0 = blockIdx.y * 128;
    if (m0 >= cnt) return;
    const int n0 = blockIdx.x * 64;

    extern __shared__ char smem[];
    const uint32_t sA = smem_u32(smem);
    const uint32_t sB = sA + NSTAGE * ABUF_H * 2;

    const int m = m0 + tid;
    const bool mvalid = m < cnt;
    const int mytok = mvalid ? g_tok[e * NTOK + m] : 0;
    const __half* ap = g_xnh + (size_t)mytok * DDIM;
    const uint32_t abytes = mvalid ? 16u : 0u;

    const __half* bp = g_w1h + (size_t)e * DDIM * HDIM +
                       (size_t)(tid >> 1) * HDIM + n0 + (tid & 1) * 32;

    float acc[4][4][4];
    #pragma unroll
    for (int mt = 0; mt < 4; mt++)
        #pragma unroll
        for (int nt = 0; nt < 4; nt++)
            #pragma unroll
            for (int q = 0; q < 4; q++) acc[mt][nt][q] = 0.f;

    gemm_mainloop(sA, sB, ap, abytes, bp, (size_t)BKH * HDIM, DDIM / BKH, acc);

    const int lane = tid & 31;
    const int warp = tid >> 5;
    const int wm64 = (warp >> 1) * 64;
    const int wn32 = (warp & 1) * 32;
    const int gr = lane >> 2, tg = lane & 3;

    const float* b1e = b1 + (size_t)e * HDIM + n0;
    #pragma unroll
    for (int mt = 0; mt < 4; mt++) {
        #pragma unroll
        for (int half = 0; half < 2; half++) {
            int mi = m0 + wm64 + mt * 16 + gr + 8 * half;
            if (mi >= cnt) continue;
            __half* hrow = g_h + ((size_t)e * NTOK + mi) * HDIM + n0;
            #pragma unroll
            for (int nt = 0; nt < 4; nt++) {
                int c = wn32 + nt * 8 + 2 * tg;
                float v0 = acc[mt][nt][2 * half + 0] + b1e[c];
                float v1 = acc[mt][nt][2 * half + 1] + b1e[c + 1];
                v0 = 0.5f * v0 * (1.0f + erff(v0 * 0.70710678118654752f));
                v1 = 0.5f * v1 * (1.0f + erff(v1 * 0.70710678118654752f));
                *(uint32_t*)(hrow + c) = pack_h2(v0, v1);
            }
        }
    }
}

// ============ GEMM 2 (split-K): out += gate * (g_h @ w2h + b2) ============
__global__ __launch_bounds__(128, 4) void gemm2_kernel(
    const float* __restrict__ b2, float* __restrict__ out)
{
    const int e = blockIdx.z >> 1;
    const int ksl = blockIdx.z & 1;
    const int cnt = g_cnt[e];
    const int m0 = blockIdx.y * 128;
    if (m0 >= cnt) return;
    const int n0 = blockIdx.x * 64;

    extern __shared__ char smem[];
    const uint32_t sA = smem_u32(smem);
    const uint32_t sB = sA + NSTAGE * ABUF_H * 2;

    const int tid = threadIdx.x;
    const int m = m0 + tid;
    const bool mvalid = m < cnt;
    const __half* ap = g_h + ((size_t)e * NTOK + (mvalid ? m : m0)) * HDIM +
                       ksl * KSLICE;
    const uint32_t abytes = mvalid ? 16u : 0u;

    const __half* bp = g_w2h + (size_t)e * HDIM * DDIM +
                       (size_t)(ksl * KSLICE + (tid >> 1)) * DDIM + n0 + (tid & 1) * 32;

    float acc[4][4][4];
    #pragma unroll
    for (int mt = 0; mt < 4; mt++)
        #pragma unroll
        for (int nt = 0; nt < 4; nt++)
            #pragma unroll
            for (int q = 0; q < 4; q++) acc[mt][nt][q] = 0.f;

    gemm_mainloop(sA, sB, ap, abytes, bp, (size_t)BKH * DDIM, KSLICE / BKH, acc);

    const int lane = tid & 31;
    const int warp = tid >> 5;
    const int wm64 = (warp >> 1) * 64;
    const int wn32 = (warp & 1) * 32;
    const int gr = lane >> 2, tg = lane & 3;

    const float* b2e = b2 + (size_t)e * DDIM + n0;
    const float bias_scale = (ksl == 0) ? 1.0f : 0.0f;
    #pragma unroll
    for (int mt = 0; mt < 4; mt++) {
        #pragma unroll
        for (int half = 0; half < 2; half++) {
            int mi = m0 + wm64 + mt * 16 + gr + 8 * half;
            if (mi >= cnt) continue;
            int token = g_tok[e * NTOK + mi];
            float gate = g_gate[e * NTOK + mi];
            float* orow = out + (size_t)token * DDIM + n0;
            #pragma unroll
            for (int nt = 0; nt < 4; nt++) {
                int c = wn32 + nt * 8 + 2 * tg;
                float v0 = acc[mt][nt][2 * half + 0] + bias_scale * b2e[c];
                float v1 = acc[mt][nt][2 * half + 1] + bias_scale * b2e[c + 1];
                atomicAdd(&orow[c], gate * v0);
                atomicAdd(&orow[c + 1], gate * v1);
            }
        }
    }
}

// ---------------- balance loss scalar ----------------
__global__ void finish_kernel(float* __restrict__ out) {
    if (threadIdx.x == 0) {
        float acc = 0.f;
        #pragma unroll
        for (int e = 0; e < NEXP; e++) acc += (float)g_cnt[e] * g_psum[e];
        out[(size_t)NTOK * DDIM] =
            0.01f * (float)NEXP * acc / ((float)NTOK * (float)NTOK);
    }
}

// ---------------- launch ----------------
extern "C" void kernel_launch(void* const* d_in, const int* in_sizes, int n_in,
                              void* d_out, int out_size)
{
    const float* x     = (const float*)d_in[0];
    const float* gamma = (const float*)d_in[1];
    const float* beta  = (const float*)d_in[2];
    const float* gw    = (const float*)d_in[3];
    const float* w1    = (const float*)d_in[4];
    const float* b1    = (const float*)d_in[5];
    const float* w2    = (const float*)d_in[6];
    const float* b2    = (const float*)d_in[7];
    float* out = (float*)d_out;

    cudaFuncSetAttribute(gemm1_kernel, cudaFuncAttributeMaxDynamicSharedMemorySize, SMEM_BYTES);
    cudaFuncSetAttribute(gemm2_kernel, cudaFuncAttributeMaxDynamicSharedMemorySize, SMEM_BYTES);

    zero_kernel<<<1, 32>>>();
    prep_kernel<<<NTOK + CONVBLKS, 256>>>(x, gamma, beta, gw,
                                          (const float4*)w1,
                                          out, out + (size_t)NTOK * DDIM + 1);

    // z slice NEXP carries the w2 convert blocks
    gemm1_kernel<<<dim3(HDIM / 64, NTOK / 128, NEXP + 1), 128, SMEM_BYTES>>>(
        b1, (const float4*)w2);
    gemm2_kernel<<<dim3(DDIM / 64, NTOK / 128, NEXP * SPLITK), 128, SMEM_BYTES>>>(b2, out);
    finish_kernel<<<1, 32>>>(out);
}

// round 10
// speedup vs baseline: 1.9749x; 1.9749x over previous
#include <cuda_runtime.h>
#include <cuda_fp16.h>
#include <math.h>
#include <stdint.h>

#define NTOK 4096
#define DDIM 1024
#define NEXP 8
#define HDIM 4096
#define BKH 64            // k per tile (halves)
#define CONVBLKS 1024
#define SPLITK 2
#define KSLICE (HDIM / SPLITK)

// ---------------- scratch ----------------
__device__ __half g_xnh[(size_t)NTOK * DDIM];                  // normalized x, fp16
__device__ __half g_w1h[(size_t)NEXP * DDIM * HDIM];           // w1 fp16
__device__ __half g_w2h[(size_t)NEXP * HDIM * DDIM];           // w2 fp16
__device__ __half g_h[(size_t)NEXP * NTOK * HDIM];             // hidden, fp16
__device__ int    g_cnt[NEXP];
__device__ float  g_psum[NEXP];
__device__ int    g_tok[NEXP * NTOK];
__device__ float  g_gate[NEXP * NTOK];

// ---------------- helpers ----------------
__device__ __forceinline__ uint32_t smem_u32(const void* p) {
    uint32_t a;
    asm("{ .reg .u64 t; cvta.to.shared.u64 t, %1; cvt.u32.u64 %0, t; }" : "=r"(a) : "l"(p));
    return a;
}
__device__ __forceinline__ uint32_t pack_h2(float a, float b) {
    __half2 h = __floats2half2_rn(a, b);
    return *(uint32_t*)&h;
}
// .cg: L2-only path (no L1 fill) — GEMM tiles have no L1 reuse
#define CP16(dst, src) \
    asm volatile("cp.async.cg.shared.global [%0], [%1], 16;" :: "r"(dst), "l"(src))
#define CP16Z(dst, src, bytes) \
    asm volatile("cp.async.cg.shared.global [%0], [%1], 16, %2;" :: "r"(dst), "l"(src), "r"(bytes))
#define CP_COMMIT() asm volatile("cp.async.commit_group;" ::: "memory")
#define CP_WAIT1()  asm volatile("cp.async.wait_group 1;" ::: "memory")

#define LDSM_X4(r0, r1, r2, r3, addr) \
    asm volatile("ldmatrix.sync.aligned.m8n8.x4.shared.b16 {%0,%1,%2,%3}, [%4];" \
        : "=r"(r0), "=r"(r1), "=r"(r2), "=r"(r3) : "r"(addr))
#define LDSM_X4T(r0, r1, r2, r3, addr) \
    asm volatile("ldmatrix.sync.aligned.m8n8.x4.trans.shared.b16 {%0,%1,%2,%3}, [%4];" \
        : "=r"(r0), "=r"(r1), "=r"(r2), "=r"(r3) : "r"(addr))

__device__ __forceinline__ void mma_f16(float* d, const uint32_t* a, const uint32_t* b) {
    asm volatile(
        "mma.sync.aligned.m16n8k16.row.col.f32.f16.f16.f32 "
        "{%0,%1,%2,%3}, {%4,%5,%6,%7}, {%8,%9}, {%0,%1,%2,%3};"
        : "+f"(d[0]), "+f"(d[1]), "+f"(d[2]), "+f"(d[3])
        : "r"(a[0]), "r"(a[1]), "r"(a[2]), "r"(a[3]), "r"(b[0]), "r"(b[1]));
}

// smem strides in halves (stride mod 128B = 16B -> conflict-free ldmatrix)
#define AST 72
#define BST 136
#define ABUF_H (128 * AST)   // halves / stage
#define BBUF_H (BKH * BST)   // halves / stage
#define NSTAGE 3
#define SMEM_BYTES ((NSTAGE * (ABUF_H + BBUF_H)) * 2 + 512 + 128)

// ---------------- reset counters ----------------
__global__ void zero_kernel() {
    int t = threadIdx.x;
    if (t < NEXP) { g_cnt[t] = 0; g_psum[t] = 0.0f; }
}

// ---------------- merged prep: LN+router+residual copy, + w1 convert ----------
__global__ __launch_bounds__(256) void prep_kernel(
    const float* __restrict__ x, const float* __restrict__ gamma,
    const float* __restrict__ beta, const float* __restrict__ gw,
    const float4* __restrict__ w1,
    float* __restrict__ out, float* __restrict__ probs_out)
{
    const int tid = threadIdx.x;

    if (blockIdx.x >= NTOK) {
        // w1 convert only (w2 converts inside gemm1's grid)
        const int n4 = NEXP * DDIM * HDIM / 4;
        uint2* o1 = (uint2*)g_w1h;
        for (int i = (blockIdx.x - NTOK) * 256 + tid; i < n4;
             i += CONVBLKS * 256) {
            float4 v = w1[i];
            uint2 o;
            o.x = pack_h2(v.x, v.y);
            o.y = pack_h2(v.z, v.w);
            o1[i] = o;
        }
        return;
    }

    const int n = blockIdx.x;
    const int lane = tid & 31, warp = tid >> 5;

    float4 v = reinterpret_cast<const float4*>(x + (size_t)n * DDIM)[tid];
    // residual base: out = x (replaces the serialized memcpy)
    reinterpret_cast<float4*>(out + (size_t)n * DDIM)[tid] = v;

    float s  = v.x + v.y + v.z + v.w;
    float ss = v.x * v.x + v.y * v.y + v.z * v.z + v.w * v.w;

    __shared__ float rs[8], rss[8];
    #pragma unroll
    for (int o = 16; o; o >>= 1) {
        s  += __shfl_down_sync(0xffffffffu, s, o);
        ss += __shfl_down_sync(0xffffffffu, ss, o);
    }
    if (lane == 0) { rs[warp] = s; rss[warp] = ss; }
    __syncthreads();

    __shared__ float s_mu, s_rstd;
    if (tid == 0) {
        float S = 0.f, SS = 0.f;
        #pragma unroll
        for (int i = 0; i < 8; i++) { S += rs[i]; SS += rss[i]; }
        float mu = S / (float)DDIM;
        float var = SS / (float)DDIM - mu * mu;
        s_mu = mu; s_rstd = rsqrtf(var + 1e-5f);
    }
    __syncthreads();
    const float mu = s_mu, r = s_rstd;

    float4 g4 = reinterpret_cast<const float4*>(gamma)[tid];
    float4 b4 = reinterpret_cast<const float4*>(beta)[tid];
    float xn0 = (v.x - mu) * r * g4.x + b4.x;
    float xn1 = (v.y - mu) * r * g4.y + b4.y;
    float xn2 = (v.z - mu) * r * g4.z + b4.z;
    float xn3 = (v.w - mu) * r * g4.w + b4.w;
    {
        uint2 o;
        o.x = pack_h2(xn0, xn1);
        o.y = pack_h2(xn2, xn3);
        reinterpret_cast<uint2*>(g_xnh + (size_t)n * DDIM)[tid] = o;
    }

    float lg[NEXP];
    {
        const float4* gwr = reinterpret_cast<const float4*>(gw + (size_t)tid * 4 * NEXP);
        float4 a0 = gwr[0], a1 = gwr[1];
        float4 c0 = gwr[2], c1 = gwr[3];
        float4 d0 = gwr[4], d1 = gwr[5];
        float4 e0 = gwr[6], e1 = gwr[7];
        lg[0] = xn0*a0.x + xn1*c0.x + xn2*d0.x + xn3*e0.x;
        lg[1] = xn0*a0.y + xn1*c0.y + xn2*d0.y + xn3*e0.y;
        lg[2] = xn0*a0.z + xn1*c0.z + xn2*d0.z + xn3*e0.z;
        lg[3] = xn0*a0.w + xn1*c0.w + xn2*d0.w + xn3*e0.w;
        lg[4] = xn0*a1.x + xn1*c1.x + xn2*d1.x + xn3*e1.x;
        lg[5] = xn0*a1.y + xn1*c1.y + xn2*d1.y + xn3*e1.y;
        lg[6] = xn0*a1.z + xn1*c1.z + xn2*d1.z + xn3*e1.z;
        lg[7] = xn0*a1.w + xn1*c1.w + xn2*d1.w + xn3*e1.w;
    }

    __shared__ float sl[8][NEXP];
    #pragma unroll
    for (int e = 0; e < NEXP; e++) {
        float t = lg[e];
        #pragma unroll
        for (int o = 16; o; o >>= 1) t += __shfl_down_sync(0xffffffffu, t, o);
        if (lane == 0) sl[warp][e] = t;
    }
    __syncthreads();

    if (tid == 0) {
        float logit[NEXP];
        #pragma unroll
        for (int e = 0; e < NEXP; e++) {
            float t = 0.f;
            #pragma unroll
            for (int w = 0; w < 8; w++) t += sl[w][e];
            logit[e] = t;
        }
        float mx = logit[0];
        #pragma unroll
        for (int e = 1; e < NEXP; e++) mx = fmaxf(mx, logit[e]);
        float p[NEXP], denom = 0.f;
        #pragma unroll
        for (int e = 0; e < NEXP; e++) { p[e] = expf(logit[e] - mx); denom += p[e]; }
        float inv = 1.0f / denom;
        #pragma unroll
        for (int e = 0; e < NEXP; e++) {
            p[e] *= inv;
            probs_out[(size_t)n * NEXP + e] = p[e];
            atomicAdd(&g_psum[e], p[e]);
        }
        int i1 = 0;
        #pragma unroll
        for (int e = 1; e < NEXP; e++) if (p[e] > p[i1]) i1 = e;
        int i2 = (i1 == 0) ? 1 : 0;
        #pragma unroll
        for (int e = 0; e < NEXP; e++) if (e != i1 && p[e] > p[i2]) i2 = e;
        float wsum = p[i1] + p[i2] + 1e-8f;
        float w1v = p[i1] / wsum, w2v = p[i2] / wsum;
        int r1 = atomicAdd(&g_cnt[i1], 1);
        g_tok[i1 * NTOK + r1] = n; g_gate[i1 * NTOK + r1] = w1v;
        int r2 = atomicAdd(&g_cnt[i2], 1);
        g_tok[i2 * NTOK + r2] = n; g_gate[i2 * NTOK + r2] = w2v;
    }
}

// ============ fp16 HMMA GEMM core: BM=128,BN=128,BK=64, 256 threads ============
// 8 warps (2x4), warp tile 64x32, 3-stage cp.async ring, ldmatrix fragments.

__device__ __forceinline__ void gemm_mainloop(
    uint32_t sA, uint32_t sB,
    const __half* aptr0, const __half* aptr1, const __half* aptr2, const __half* aptr3,
    uint32_t ab0, uint32_t ab1, uint32_t ab2, uint32_t ab3,
    const __half* bptr0, const __half* bptr1, const __half* bptr2, const __half* bptr3,
    size_t b_adv,
    int NK, float acc[4][4][4])
{
    const int tid = threadIdx.x;
    const int lane = tid & 31;
    const int warp = tid >> 5;
    const int wm64 = (warp >> 2) * 64;
    const int wn32 = (warp & 3) * 32;

    const uint32_t a_soff = (uint32_t)(((tid >> 3) * AST + (tid & 7) * 8) * 2);
    const uint32_t b_soff = (uint32_t)(((tid >> 4) * BST + (tid & 15) * 8) * 2);
    const uint32_t a_rstep = (uint32_t)(32 * AST * 2);
    const uint32_t b_rstep = (uint32_t)(16 * BST * 2);

    const int lrow = (lane & 7) + 8 * ((lane >> 3) & 1);
    const int lhi  = 8 * (lane >> 4);
    uint32_t aoff[4], boff[2];
    #pragma unroll
    for (int mt = 0; mt < 4; mt++)
        aoff[mt] = (uint32_t)(((wm64 + mt * 16 + lrow) * AST + lhi) * 2);
    #pragma unroll
    for (int np = 0; np < 2; np++)
        boff[np] = (uint32_t)((lrow * BST + wn32 + np * 16 + lhi) * 2);

    const __half* ap[4] = {aptr0, aptr1, aptr2, aptr3};
    uint32_t ab[4] = {ab0, ab1, ab2, ab3};
    const __half* bp[4] = {bptr0, bptr1, bptr2, bptr3};

    // prologue: tiles 0 and 1
    #pragma unroll
    for (int st = 0; st < 2; st++) {
        uint32_t dA = sA + st * (ABUF_H * 2) + a_soff;
        uint32_t dB = sB + st * (BBUF_H * 2) + b_soff;
        #pragma unroll
        for (int i = 0; i < 4; i++) {
            CP16Z(dA + i * a_rstep, ap[i], ab[i]); ap[i] += BKH;
        }
        #pragma unroll
        for (int i = 0; i < 4; i++) {
            CP16(dB + i * b_rstep, bp[i]); bp[i] += b_adv;
        }
        CP_COMMIT();
    }

    for (int ic = 0; ic < NK; ic++) {
        CP_WAIT1();
        __syncthreads();

        if (ic + 2 < NK) {
            const int st = (ic + 2) % NSTAGE;
            uint32_t dA = sA + st * (ABUF_H * 2) + a_soff;
            uint32_t dB = sB + st * (BBUF_H * 2) + b_soff;
            #pragma unroll
            for (int i = 0; i < 4; i++) {
                CP16Z(dA + i * a_rstep, ap[i], ab[i]); ap[i] += BKH;
            }
            #pragma unroll
            for (int i = 0; i < 4; i++) {
                CP16(dB + i * b_rstep, bp[i]); bp[i] += b_adv;
            }
        }
        CP_COMMIT();

        const uint32_t sAt = sA + (ic % NSTAGE) * (ABUF_H * 2);
        const uint32_t sBt = sB + (ic % NSTAGE) * (BBUF_H * 2);
        #pragma unroll
        for (int ks = 0; ks < 4; ks++) {
            uint32_t af[4][4], bf[2][4];
            #pragma unroll
            for (int mt = 0; mt < 4; mt++)
                LDSM_X4(af[mt][0], af[mt][1], af[mt][2], af[mt][3],
                        sAt + aoff[mt] + ks * 32);
            #pragma unroll
            for (int np = 0; np < 2; np++)
                LDSM_X4T(bf[np][0], bf[np][1], bf[np][2], bf[np][3],
                         sBt + boff[np] + ks * 16 * BST * 2);
            #pragma unroll
            for (int mt = 0; mt < 4; mt++)
                #pragma unroll
                for (int nt = 0; nt < 4; nt++)
                    mma_f16(acc[mt][nt], af[mt], &bf[nt >> 1][(nt & 1) * 2]);
        }
    }
}

// ============ GEMM 1: g_h = gelu(gather(g_xnh) @ w1h + b1)  (+ w2 convert) ====
__global__ __launch_bounds__(256, 2) void gemm1_kernel(
    const float* __restrict__ b1, const float4* __restrict__ w2)
{
    const int tid = threadIdx.x;

    if (blockIdx.z == NEXP) {
        // w2 fp32->fp16 convert riding in gemm1's grid
        const int n4 = NEXP * HDIM * DDIM / 4;
        uint2* o2 = (uint2*)g_w2h;
        const int nblk = gridDim.x * gridDim.y;
        const int bid = blockIdx.y * gridDim.x + blockIdx.x;
        for (int i = bid * 256 + tid; i < n4; i += nblk * 256) {
            float4 v = w2[i];
            uint2 o;
            o.x = pack_h2(v.x, v.y);
            o.y = pack_h2(v.z, v.w);
            o2[i] = o;
        }
        return;
    }

    const int e = blockIdx.z;
    const int cnt = g_cnt[e];
    const int m0 = blockIdx.y * 128;
    if (m0 >= cnt) return;
    const int n0 = blockIdx.x * 128;

    extern __shared__ char smem[];
    const uint32_t sA = smem_u32(smem);
    const uint32_t sB = sA + NSTAGE * ABUF_H * 2;
    int* s_tok = (int*)(smem + NSTAGE * (ABUF_H + BBUF_H) * 2);

    if (tid < 128)
        s_tok[tid] = (m0 + tid < cnt) ? g_tok[e * NTOK + m0 + tid] : 0;
    __syncthreads();

    const int arow = tid >> 3;
    const int acol = (tid & 7) * 8;
    const __half* ap[4];
    uint32_t ab[4];
    #pragma unroll
    for (int i = 0; i < 4; i++) {
        int m = m0 + arow + 32 * i;
        bool valid = m < cnt;
        ap[i] = g_xnh + (size_t)s_tok[arow + 32 * i] * DDIM + acol;
        ab[i] = valid ? 16u : 0u;
    }
    const int brow = tid >> 4;
    const int bcol = (tid & 15) * 8;
    const __half* bp[4];
    #pragma unroll
    for (int i = 0; i < 4; i++)
        bp[i] = g_w1h + (size_t)e * DDIM * HDIM + (size_t)(brow + 16 * i) * HDIM + n0 + bcol;

    float acc[4][4][4];
    #pragma unroll
    for (int mt = 0; mt < 4; mt++)
        #pragma unroll
        for (int nt = 0; nt < 4; nt++)
            #pragma unroll
            for (int q = 0; q < 4; q++) acc[mt][nt][q] = 0.f;

    gemm_mainloop(sA, sB, ap[0], ap[1], ap[2], ap[3], ab[0], ab[1], ab[2], ab[3],
                  bp[0], bp[1], bp[2], bp[3], (size_t)BKH * HDIM,
                  DDIM / BKH, acc);

    const int lane = tid & 31;
    const int warp = tid >> 5;
    const int wm64 = (warp >> 2) * 64;
    const int wn32 = (warp & 3) * 32;
    const int gr = lane >> 2, tg = lane & 3;

    const float* b1e = b1 + (size_t)e * HDIM + n0;
    #pragma unroll
    for (int mt = 0; mt < 4; mt++) {
        #pragma unroll
        for (int half = 0; half < 2; half++) {
            int m = m0 + wm64 + mt * 16 + gr + 8 * half;
            if (m >= cnt) continue;
            __half* hrow = g_h + ((size_t)e * NTOK + m) * HDIM + n0;
            #pragma unroll
            for (int nt = 0; nt < 4; nt++) {
                int c = wn32 + nt * 8 + 2 * tg;
                float v0 = acc[mt][nt][2 * half + 0] + b1e[c];
                float v1 = acc[mt][nt][2 * half + 1] + b1e[c + 1];
                v0 = 0.5f * v0 * (1.0f + erff(v0 * 0.70710678118654752f));
                v1 = 0.5f * v1 * (1.0f + erff(v1 * 0.70710678118654752f));
                *(uint32_t*)(hrow + c) = pack_h2(v0, v1);
            }
        }
    }
}

// ============ GEMM 2 (split-K): out += gate * (g_h @ w2h + b2) ============
__global__ __launch_bounds__(256, 2) void gemm2_kernel(
    const float* __restrict__ b2, float* __restrict__ out)
{
    const int e = blockIdx.z >> 1;
    const int ksl = blockIdx.z & 1;
    const int cnt = g_cnt[e];
    const int m0 = blockIdx.y * 128;
    if (m0 >= cnt) return;
    const int n0 = blockIdx.x * 128;

    extern __shared__ char smem[];
    const uint32_t sA = smem_u32(smem);
    const uint32_t sB = sA + NSTAGE * ABUF_H * 2;

    const int tid = threadIdx.x;

    const int arow = tid >> 3;
    const int acol = (tid & 7) * 8;
    const __half* ap[4];
    uint32_t ab[4];
    #pragma unroll
    for (int i = 0; i < 4; i++) {
        int m = m0 + arow + 32 * i;
        bool valid = m < cnt;
        ap[i] = g_h + ((size_t)e * NTOK + (valid ? m : m0)) * HDIM +
                ksl * KSLICE + acol;
        ab[i] = valid ? 16u : 0u;
    }
    const int brow = tid >> 4;
    const int bcol = (tid & 15) * 8;
    const __half* bp[4];
    #pragma unroll
    for (int i = 0; i < 4; i++)
        bp[i] = g_w2h + (size_t)e * HDIM * DDIM +
                (size_t)(ksl * KSLICE + brow + 16 * i) * DDIM + n0 + bcol;

    float acc[4][4][4];
    #pragma unroll
    for (int mt = 0; mt < 4; mt++)
        #pragma unroll
        for (int nt = 0; nt < 4; nt++)
            #pragma unroll
            for (int q = 0; q < 4; q++) acc[mt][nt][q] = 0.f;

    gemm_mainloop(sA, sB, ap[0], ap[1], ap[2], ap[3], ab[0], ab[1], ab[2], ab[3],
                  bp[0], bp[1], bp[2], bp[3], (size_t)BKH * DDIM,
                  KSLICE / BKH, acc);

    const int lane = tid & 31;
    const int warp = tid >> 5;
    const int wm64 = (warp >> 2) * 64;
    const int wn32 = (warp & 3) * 32;
    const int gr = lane >> 2, tg = lane & 3;

    const float* b2e = b2 + (size_t)e * DDIM + n0;
    const float bias_scale = (ksl == 0) ? 1.0f : 0.0f;
    #pragma unroll
    for (int mt = 0; mt < 4; mt++) {
        #pragma unroll
        for (int half = 0; half < 2; half++) {
            int m = m0 + wm64 + mt * 16 + gr + 8 * half;
            if (m >= cnt) continue;
            int token = g_tok[e * NTOK + m];
            float gate = g_gate[e * NTOK + m];
            float* orow = out + (size_t)token * DDIM + n0;
            #pragma unroll
            for (int nt = 0; nt < 4; nt++) {
                int c = wn32 + nt * 8 + 2 * tg;
                float v0 = acc[mt][nt][2 * half + 0] + bias_scale * b2e[c];
                float v1 = acc[mt][nt][2 * half + 1] + bias_scale * b2e[c + 1];
                atomicAdd(&orow[c], gate * v0);
                atomicAdd(&orow[c + 1], gate * v1);
            }
        }
    }
}

// ---------------- balance loss scalar ----------------
__global__ void finish_kernel(float* __restrict__ out) {
    if (threadIdx.x == 0) {
        float acc = 0.f;
        #pragma unroll
        for (int e = 0; e < NEXP; e++) acc += (float)g_cnt[e] * g_psum[e];
        out[(size_t)NTOK * DDIM] =
            0.01f * (float)NEXP * acc / ((float)NTOK * (float)NTOK);
    }
}

// ---------------- launch ----------------
extern "C" void kernel_launch(void* const* d_in, const int* in_sizes, int n_in,
                              void* d_out, int out_size)
{
    const float* x     = (const float*)d_in[0];
    const float* gamma = (const float*)d_in[1];
    const float* beta  = (const float*)d_in[2];
    const float* gw    = (const float*)d_in[3];
    const float* w1    = (const float*)d_in[4];
    const float* b1    = (const float*)d_in[5];
    const float* w2    = (const float*)d_in[6];
    const float* b2    = (const float*)d_in[7];
    float* out = (float*)d_out;

    cudaFuncSetAttribute(gemm1_kernel, cudaFuncAttributeMaxDynamicSharedMemorySize, SMEM_BYTES);
    cudaFuncSetAttribute(gemm2_kernel, cudaFuncAttributeMaxDynamicSharedMemorySize, SMEM_BYTES);

    zero_kernel<<<1, 32>>>();
    prep_kernel<<<NTOK + CONVBLKS, 256>>>(x, gamma, beta, gw,
                                          (const float4*)w1,
                                          out, out + (size_t)NTOK * DDIM + 1);

    // z slice NEXP carries the w2 convert blocks
    gemm1_kernel<<<dim3(HDIM / 128, NTOK / 128, NEXP + 1), 256, SMEM_BYTES>>>(
        b1, (const float4*)w2);
    gemm2_kernel<<<dim3(DDIM / 128, NTOK / 128, NEXP * SPLITK), 256, SMEM_BYTES>>>(b2, out);
    finish_kernel<<<1, 32>>>(out);
}